// round 15
// baseline (speedup 1.0000x reference)
#include <cuda_runtime.h>
#include <math.h>

#define N_NODES 50000
#define N_EDGES 800000
#define SCAN_B  1024
#define SCAN_NT ((N_NODES + SCAN_B - 1) / SCAN_B)   // 49 tiles

// griddepcontrol (PDL)
#define PDL_TRIGGER() asm volatile("griddepcontrol.launch_dependents;" ::: "memory")
#define PDL_WAIT()    asm volatile("griddepcontrol.wait;" ::: "memory")

// ---------------- scratch (static device memory; no allocs) ----------------
__device__ int      g_counts[N_NODES];     // invariant: zero at kernel_launch entry
__device__ int      g_rowptr[N_NODES + 1];
__device__ int      g_rsv[N_EDGES];        // per-edge ticket within its dst segment
__device__ int2     g_edge[N_EDGES];       // {src, weight-as-int}
__device__ float    g_x16[N_NODES * 16];   // x padded 13 -> 16
__device__ float    g_h[2][N_NODES * 64];  // fp32 h
// aggr stored pre-split: per node row, words [0,32) = bf16x2 hi, [32,64) = lo.
__device__ unsigned g_aggrbf[N_NODES * 64];
__device__ float    g_t[N_NODES];
__device__ float    g_r[N_NODES];

// ---------------- helpers ----------------
__device__ __forceinline__ unsigned cvt_bf2(float lo, float hi) {
    unsigned r;
    asm("cvt.rn.bf16x2.f32 %0, %1, %2;" : "=r"(r) : "f"(hi), "f"(lo));
    return r;
}
__device__ __forceinline__ float bf_lo(unsigned u) { return __uint_as_float(u << 16); }
__device__ __forceinline__ float bf_hi(unsigned u) { return __uint_as_float(u & 0xffff0000u); }

__device__ __forceinline__ void mma_bf16(float* c,
                                         unsigned a0, unsigned a1, unsigned a2, unsigned a3,
                                         unsigned b0, unsigned b1) {
    asm volatile(
        "mma.sync.aligned.m16n8k16.row.col.f32.bf16.bf16.f32 "
        "{%0,%1,%2,%3}, {%4,%5,%6,%7}, {%8,%9}, {%0,%1,%2,%3};\n"
        : "+f"(c[0]), "+f"(c[1]), "+f"(c[2]), "+f"(c[3])
        : "r"(a0), "r"(a1), "r"(a2), "r"(a3), "r"(b0), "r"(b1));
}

// ---------------- CSR build -------------------------------------------------
// hist: padx + counts histogram + reservation tickets (R14 exact)
__global__ void k_hist(const int* __restrict__ dst, const float* __restrict__ x) {
    PDL_TRIGGER();
    int gt = blockIdx.x * blockDim.x + threadIdx.x;
    int gs = gridDim.x * blockDim.x;
    for (int i = gt; i < N_NODES * 4; i += gs) {      // input-only: pre-wait
        int node = i >> 2, c = (i & 3) * 4;
        float4 v;
        v.x = (c + 0 < 13) ? __ldg(&x[node * 13 + c + 0]) : 0.f;
        v.y = (c + 1 < 13) ? __ldg(&x[node * 13 + c + 1]) : 0.f;
        v.z = (c + 2 < 13) ? __ldg(&x[node * 13 + c + 2]) : 0.f;
        v.w = (c + 3 < 13) ? __ldg(&x[node * 13 + c + 3]) : 0.f;
        ((float4*)g_x16)[i] = v;
    }
    int e2 = gt;
    int2 d = make_int2(0, 0);
    bool ok = (2 * e2 < N_EDGES);
    if (ok) d = __ldg((const int2*)dst + e2);
    PDL_WAIT();
    if (ok) {
        int t0 = atomicAdd(&g_counts[d.x], 1);
        int t1 = atomicAdd(&g_counts[d.y], 1);
        *(int2*)(g_rsv + 2 * e2) = make_int2(t0, t1);
    }
}

// single-block monolithic scan: 49 sequential tiles, carry in smem.
// No inter-block sync -> no deadlock risk. Writes rowptr, restores counts=0.
__global__ void k_scan_mono() {
    PDL_TRIGGER();
    __shared__ int swarp[32];
    __shared__ int scarry;
    int tid = threadIdx.x, lane = tid & 31, wid = tid >> 5;
    if (tid == 0) scarry = 0;
    PDL_WAIT();
    __syncthreads();
    for (int t = 0; t < SCAN_NT; t++) {
        int i = t * SCAN_B + tid;
        int v = (i < N_NODES) ? g_counts[i] : 0;
        int sv = v;
#pragma unroll
        for (int o = 1; o < 32; o <<= 1) {
            int u = __shfl_up_sync(0xffffffffu, sv, o);
            if (lane >= o) sv += u;
        }
        if (lane == 31) swarp[wid] = sv;
        __syncthreads();
        if (wid == 0) {
            int w = swarp[lane];
#pragma unroll
            for (int o = 1; o < 32; o <<= 1) {
                int u = __shfl_up_sync(0xffffffffu, w, o);
                if (lane >= o) w += u;
            }
            swarp[lane] = w;
        }
        __syncthreads();
        int incl = sv + ((wid > 0) ? swarp[wid - 1] : 0);
        int total = swarp[31];
        int carry = scarry;
        if (i < N_NODES) {
            g_rowptr[i] = carry + incl - v;
            g_counts[i] = 0;               // restore invariant for next replay
            if (i == N_NODES - 1) g_rowptr[N_NODES] = carry + incl;
        }
        __syncthreads();
        if (tid == 0) scarry = carry + total;
        __syncthreads();
    }
}

// scatter: ticketed, atomic-free (R14 exact)
__global__ void k_scatter(const int* __restrict__ src, const int* __restrict__ dst,
                          const float* __restrict__ ew) {
    PDL_TRIGGER();
    int e2 = blockIdx.x * blockDim.x + threadIdx.x;
    bool ok = (2 * e2 < N_EDGES);
    int2 s = make_int2(0, 0), d = make_int2(0, 0);
    float2 w = make_float2(0.f, 0.f);
    if (ok) {                              // harness inputs: pre-wait safe
        s = __ldg((const int2*)src + e2);
        d = __ldg((const int2*)dst + e2);
        w = __ldg((const float2*)ew + e2);
    }
    PDL_WAIT();
    if (ok) {
        int2 r = *(const int2*)(g_rsv + 2 * e2);
        g_edge[g_rowptr[d.x] + r.x] = make_int2(s.x, __float_as_int(w.x));
        g_edge[g_rowptr[d.y] + r.y] = make_int2(s.y, __float_as_int(w.y));
    }
}

// ---------------- aggregation: full warp per node (R14 exact) --------------
__global__ void k_aggr64(int sel) {
    PDL_TRIGGER();
    PDL_WAIT();
    int w = (blockIdx.x * blockDim.x + threadIdx.x) >> 5;
    if (w >= N_NODES) return;
    int lane = threadIdx.x & 31, half = lane >> 4, sl = lane & 15;
    const float4* __restrict__ h4 = (const float4*)g_h[sel];
    int i = g_rowptr[w] + half, e = g_rowptr[w + 1];
    float4 a = make_float4(0.f, 0.f, 0.f, 0.f);
    float4 b = make_float4(0.f, 0.f, 0.f, 0.f);
    for (; i + 2 < e; i += 4) {
        int2 r0 = __ldg(&g_edge[i]);
        int2 r1 = __ldg(&g_edge[i + 2]);
        float4 v0 = __ldg(h4 + r0.x * 16 + sl);
        float4 v1 = __ldg(h4 + r1.x * 16 + sl);
        float w0 = __int_as_float(r0.y), w1 = __int_as_float(r1.y);
        a.x += w0 * v0.x; a.y += w0 * v0.y; a.z += w0 * v0.z; a.w += w0 * v0.w;
        b.x += w1 * v1.x; b.y += w1 * v1.y; b.z += w1 * v1.z; b.w += w1 * v1.w;
    }
    if (i < e) {
        int2 r = __ldg(&g_edge[i]);
        float4 v = __ldg(h4 + r.x * 16 + sl);
        float ww = __int_as_float(r.y);
        a.x += ww * v.x; a.y += ww * v.y; a.z += ww * v.z; a.w += ww * v.w;
    }
    a.x += b.x; a.y += b.y; a.z += b.z; a.w += b.w;
    a.x += __shfl_xor_sync(0xffffffffu, a.x, 16);
    a.y += __shfl_xor_sync(0xffffffffu, a.y, 16);
    a.z += __shfl_xor_sync(0xffffffffu, a.z, 16);
    a.w += __shfl_xor_sync(0xffffffffu, a.w, 16);
    if (half == 0) {
        unsigned h0 = cvt_bf2(a.x, a.y);
        unsigned h1 = cvt_bf2(a.z, a.w);
        unsigned l0 = cvt_bf2(a.x - bf_lo(h0), a.y - bf_hi(h0));
        unsigned l1 = cvt_bf2(a.z - bf_lo(h1), a.w - bf_hi(h1));
        unsigned* ob = g_aggrbf + (size_t)w * 64;
        *(uint2*)(ob + 2 * sl)      = make_uint2(h0, h1);
        *(uint2*)(ob + 32 + 2 * sl) = make_uint2(l0, l1);
    }
}

// ---------------- fused layer 0: aggregate(13) + dual-GEMM 13->64 (R14) ----
__global__ __launch_bounds__(256) void k_layer0(
    const float* __restrict__ x,
    const float* __restrict__ Wrel, const float* __restrict__ brel,
    const float* __restrict__ Wroot) {
    PDL_TRIGGER();
    __shared__ __align__(16) float sW[2 * 13 * 64];
    __shared__ float sb[64];
    __shared__ __align__(16) float sA[64 * 20];
    int tid = threadIdx.x, lane = tid & 31, wid = tid >> 5;
    for (int idx = tid; idx < 13 * 64; idx += 256) {   // harness inputs
        sW[idx]           = Wrel[idx];
        sW[13 * 64 + idx] = Wroot[idx];
    }
    if (tid < 64) sb[tid] = brel[tid];
    PDL_WAIT();

    {
        int grp = lane >> 2, sl = lane & 3;
        const float4* __restrict__ x4 = (const float4*)g_x16;
        for (int n = 0; n < 8; n++) {
            int loc = wid * 8 + n;
            int node = blockIdx.x * 64 + loc;
            float4 a = make_float4(0.f, 0.f, 0.f, 0.f);
            if (node < N_NODES) {
                int i = g_rowptr[node] + grp, e = g_rowptr[node + 1];
                for (; i < e; i += 8) {
                    int2 r = __ldg(&g_edge[i]);
                    float4 v = __ldg(x4 + r.x * 4 + sl);
                    float ww = __int_as_float(r.y);
                    a.x += ww * v.x; a.y += ww * v.y; a.z += ww * v.z; a.w += ww * v.w;
                }
            }
#pragma unroll
            for (int o = 4; o < 32; o <<= 1) {
                a.x += __shfl_xor_sync(0xffffffffu, a.x, o);
                a.y += __shfl_xor_sync(0xffffffffu, a.y, o);
                a.z += __shfl_xor_sync(0xffffffffu, a.z, o);
                a.w += __shfl_xor_sync(0xffffffffu, a.w, o);
            }
            if (grp == 0) *(float4*)(sA + loc * 20 + sl * 4) = a;
        }
    }
    __syncthreads();

    int loc  = tid >> 2;
    int node = blockIdx.x * 64 + loc;
    int cq   = (tid & 3) * 4;
    int c0   = cq * 4;
    if (node >= N_NODES) return;
    float acc[16];
#pragma unroll
    for (int j = 0; j < 16; j++) acc[j] = sb[c0 + j];
    const float4* sWrel4  = (const float4*)sW;
    const float4* sWroot4 = (const float4*)(sW + 13 * 64);
#pragma unroll
    for (int k = 0; k < 13; k++) {
        float a  = sA[loc * 20 + k];
        float hk = __ldg(&x[node * 13 + k]);
#pragma unroll
        for (int j = 0; j < 4; j++) {
            float4 wr = sWrel4[k * 16 + cq + j];
            float4 ws = sWroot4[k * 16 + cq + j];
            acc[4 * j + 0] += a * wr.x + hk * ws.x;
            acc[4 * j + 1] += a * wr.y + hk * ws.y;
            acc[4 * j + 2] += a * wr.z + hk * ws.z;
            acc[4 * j + 3] += a * wr.w + hk * ws.w;
        }
    }
    float4* o4 = (float4*)(g_h[0] + (size_t)node * 64 + c0);
#pragma unroll
    for (int j = 0; j < 4; j++) {
        float4 v;
        v.x = fmaxf(acc[4 * j + 0], 0.f); v.y = fmaxf(acc[4 * j + 1], 0.f);
        v.z = fmaxf(acc[4 * j + 2], 0.f); v.w = fmaxf(acc[4 * j + 3], 0.f);
        o4[j] = v;
    }
}

// ---------------- GEMM 64->64 via bf16 3-term MMA (R14 exact) --------------
#define AW 68   // padded word stride (bank-conflict-free fragment loads)
template <bool FINAL>
__global__ __launch_bounds__(256) void k_gemm64_mma(
    const float* __restrict__ Wrel, const float* __restrict__ brel,
    const float* __restrict__ Wroot,
    const float* __restrict__ Wrel4, const float* __restrict__ b4,
    const float* __restrict__ Wroot4,
    int insel, int outsel) {
    PDL_TRIGGER();
    extern __shared__ unsigned smem_u[];
    unsigned* sAhi = smem_u;                    // 128*AW
    unsigned* sAlo = sAhi + 128 * AW;           // 128*AW
    unsigned* sWhi = sAlo + 128 * AW;           // 64*AW
    unsigned* sWlo = sWhi + 64 * AW;            // 64*AW
    float*    sb   = (float*)(sWlo + 64 * AW);  // 64

    int tid = threadIdx.x;
    const float* __restrict__ hin = g_h[insel];
    int nbase = blockIdx.x * 128;

    if (tid < 64) sb[tid] = brel[tid];

    for (int p = tid; p < 64 * 64; p += 256) {    // harness inputs: pre-wait
        int col = p >> 6, w = p & 63;
        int k = 2 * w;
        float f0, f1;
        if (k < 64) { f0 = __ldg(&Wrel[k * 64 + col]);         f1 = __ldg(&Wrel[(k + 1) * 64 + col]); }
        else        { f0 = __ldg(&Wroot[(k - 64) * 64 + col]); f1 = __ldg(&Wroot[(k - 63) * 64 + col]); }
        unsigned hi = cvt_bf2(f0, f1);
        sWhi[col * AW + w] = hi;
        sWlo[col * AW + w] = cvt_bf2(f0 - bf_lo(hi), f1 - bf_hi(hi));
    }
    PDL_WAIT();
    for (int p = tid; p < 128 * 16; p += 256) {
        int ln = p >> 4, w4 = p & 15;             // words 2*w4, 2*w4+1
        int node = nbase + ln;
        if (node >= N_NODES) node = N_NODES - 1;
        // aggr half: pre-split hi/lo, straight copy
        const unsigned* ar = g_aggrbf + (size_t)node * 64;
        uint2 ah = __ldg((const uint2*)ar + w4);
        uint2 al = __ldg((const uint2*)(ar + 32) + w4);
        sAhi[ln * AW + 2 * w4]     = ah.x;
        sAhi[ln * AW + 2 * w4 + 1] = ah.y;
        sAlo[ln * AW + 2 * w4]     = al.x;
        sAlo[ln * AW + 2 * w4 + 1] = al.y;
        // h half: fp32, split here
        float4 vh = __ldg((const float4*)(hin + (size_t)node * 64) + w4);
        unsigned h0 = cvt_bf2(vh.x, vh.y), h1 = cvt_bf2(vh.z, vh.w);
        sAhi[ln * AW + 32 + 2 * w4]     = h0;
        sAhi[ln * AW + 32 + 2 * w4 + 1] = h1;
        sAlo[ln * AW + 32 + 2 * w4]     = cvt_bf2(vh.x - bf_lo(h0), vh.y - bf_hi(h0));
        sAlo[ln * AW + 32 + 2 * w4 + 1] = cvt_bf2(vh.z - bf_lo(h1), vh.w - bf_hi(h1));
    }
    __syncthreads();

    int warp = tid >> 5, lane = tid & 31;
    int r = lane >> 2, q = lane & 3;
    int mb = warp * 16;

    float acc[8][4];
#pragma unroll
    for (int j = 0; j < 8; j++) {
        float b0 = sb[j * 8 + 2 * q], b1 = sb[j * 8 + 2 * q + 1];
        acc[j][0] = b0; acc[j][1] = b1; acc[j][2] = b0; acc[j][3] = b1;
    }

    int arow0 = (mb + r) * AW, arow1 = (mb + r + 8) * AW;
#pragma unroll
    for (int ks = 0; ks < 8; ks++) {
        int kw = ks * 8 + q;
        unsigned ah0 = sAhi[arow0 + kw],     ah1 = sAhi[arow1 + kw];
        unsigned ah2 = sAhi[arow0 + kw + 4], ah3 = sAhi[arow1 + kw + 4];
        unsigned al0 = sAlo[arow0 + kw],     al1 = sAlo[arow1 + kw];
        unsigned al2 = sAlo[arow0 + kw + 4], al3 = sAlo[arow1 + kw + 4];
#pragma unroll
        for (int j = 0; j < 8; j++) {
            int brow = (j * 8 + r) * AW + ks * 8 + q;
            unsigned bh0 = sWhi[brow], bh1 = sWhi[brow + 4];
            unsigned bl0 = sWlo[brow], bl1 = sWlo[brow + 4];
            mma_bf16(acc[j], ah0, ah1, ah2, ah3, bh0, bh1);
            mma_bf16(acc[j], ah0, ah1, ah2, ah3, bl0, bl1);
            mma_bf16(acc[j], al0, al1, al2, al3, bh0, bh1);
        }
    }

    int n0 = nbase + mb + r;      // row of c0/c1
    int n1 = n0 + 8;              // row of c2/c3
    if (FINAL) {
        float pt0 = 0.f, pr0 = 0.f, pt1 = 0.f, pr1 = 0.f;
#pragma unroll
        for (int j = 0; j < 8; j++) {
            int c = j * 8 + 2 * q;
            float w0 = __ldg(&Wrel4[c]),  w1 = __ldg(&Wrel4[c + 1]);
            float s0 = __ldg(&Wroot4[c]), s1 = __ldg(&Wroot4[c + 1]);
            float u;
            u = fmaxf(acc[j][0], 0.f); pt0 += u * w0; pr0 += u * s0;
            u = fmaxf(acc[j][1], 0.f); pt0 += u * w1; pr0 += u * s1;
            u = fmaxf(acc[j][2], 0.f); pt1 += u * w0; pr1 += u * s0;
            u = fmaxf(acc[j][3], 0.f); pt1 += u * w1; pr1 += u * s1;
        }
        pt0 += __shfl_xor_sync(0xffffffffu, pt0, 1);
        pt0 += __shfl_xor_sync(0xffffffffu, pt0, 2);
        pr0 += __shfl_xor_sync(0xffffffffu, pr0, 1);
        pr0 += __shfl_xor_sync(0xffffffffu, pr0, 2);
        pt1 += __shfl_xor_sync(0xffffffffu, pt1, 1);
        pt1 += __shfl_xor_sync(0xffffffffu, pt1, 2);
        pr1 += __shfl_xor_sync(0xffffffffu, pr1, 1);
        pr1 += __shfl_xor_sync(0xffffffffu, pr1, 2);
        float bb = __ldg(&b4[0]);
        if (q == 0) {
            if (n0 < N_NODES) { g_t[n0] = pt0; g_r[n0] = pr0 + bb; }
            if (n1 < N_NODES) { g_t[n1] = pt1; g_r[n1] = pr1 + bb; }
        }
    } else {
        float* ob = g_h[outsel];
#pragma unroll
        for (int j = 0; j < 8; j++) {
            int c = j * 8 + 2 * q;
            if (n0 < N_NODES)
                *(float2*)(ob + (size_t)n0 * 64 + c) =
                    make_float2(fmaxf(acc[j][0], 0.f), fmaxf(acc[j][1], 0.f));
            if (n1 < N_NODES)
                *(float2*)(ob + (size_t)n1 * 64 + c) =
                    make_float2(fmaxf(acc[j][2], 0.f), fmaxf(acc[j][3], 0.f));
        }
    }
}

// ---------------- final: out = sigmoid(segsum(w * t[src]) + r) -------------
__global__ void k_final(float* __restrict__ out) {
    PDL_TRIGGER();
    PDL_WAIT();
    int gw   = (blockIdx.x * blockDim.x + threadIdx.x) >> 5;
    int lane = threadIdx.x & 31;
    if (gw >= N_NODES) return;
    int start = g_rowptr[gw], end = g_rowptr[gw + 1];
    float acc = 0.f;
    for (int e = start + lane; e < end; e += 32) {
        int2 er = __ldg(&g_edge[e]);
        acc += __int_as_float(er.y) * __ldg(&g_t[er.x]);
    }
#pragma unroll
    for (int o = 16; o > 0; o >>= 1)
        acc += __shfl_xor_sync(0xffffffffu, acc, o);
    if (lane == 0) {
        float z = acc + g_r[gw];
        out[gw] = 1.f / (1.f + expf(-z));
    }
}

// ---------------- launch helpers ----------------
template <typename F, typename... Args>
static void launch_pdl(F f, dim3 g, dim3 b, size_t sm, Args... args) {
    cudaLaunchConfig_t cfg = {};
    cfg.gridDim = g;
    cfg.blockDim = b;
    cfg.dynamicSmemBytes = sm;
    cfg.stream = 0;
    cudaLaunchAttribute at[1];
    at[0].id = cudaLaunchAttributeProgrammaticStreamSerialization;
    at[0].val.programmaticStreamSerializationAllowed = 1;
    cfg.attrs = at;
    cfg.numAttrs = 1;
    cudaLaunchKernelEx(&cfg, f, args...);
}

extern "C" void kernel_launch(void* const* d_in, const int* in_sizes, int n_in,
                              void* d_out, int out_size) {
    const float* x  = (const float*)d_in[0];
    const int*   ei = (const int*)d_in[1];
    const float* ew = (const float*)d_in[2];
    const int* src = ei;
    const int* dst = ei + N_EDGES;

    const float* Wrel[5], * brel[5], * Wroot[5];
    for (int l = 0; l < 5; l++) {
        Wrel[l]  = (const float*)d_in[3 + 3 * l];
        brel[l]  = (const float*)d_in[4 + 3 * l];
        Wroot[l] = (const float*)d_in[5 + 3 * l];
    }
    float* out = (float*)d_out;

    const int SMEM_MMA = (128 * AW * 2 + 64 * AW * 2 + 64) * 4;   // 104704 B
    cudaFuncSetAttribute(k_gemm64_mma<false>,
                         cudaFuncAttributeMaxDynamicSharedMemorySize, SMEM_MMA);
    cudaFuncSetAttribute(k_gemm64_mma<true>,
                         cudaFuncAttributeMaxDynamicSharedMemorySize, SMEM_MMA);

    const int TB = 256;
    dim3 B(TB);
    int gE2  = (N_EDGES / 2 + TB - 1) / TB;       // 2 edges/thread (covers padx)
    int gW   = (N_NODES * 32 + TB - 1) / TB;      // warp-per-node
    int g64  = (N_NODES + 63) / 64;
    int g128 = (N_NODES + 127) / 128;

    // CSR build (g_counts zero by invariant); scan is one single-block kernel
    launch_pdl(k_hist, dim3(gE2), B, 0, dst, x);
    launch_pdl(k_scan_mono, dim3(1), dim3(SCAN_B), 0);
    launch_pdl(k_scatter, dim3(gE2), B, 0, src, dst, ew);

    // layer 0: 13 -> 64 (fused aggregation + GEMM) — now the 4th launch
    launch_pdl(k_layer0, dim3(g64), B, 0, x, Wrel[0], brel[0], Wroot[0]);

    // layers 1-3: 64 -> 64 (layer 3 folds the 64->1 projection of layer 4)
    launch_pdl(k_aggr64, dim3(gW), B, 0, 0);
    launch_pdl(k_gemm64_mma<false>, dim3(g128), B, (size_t)SMEM_MMA,
               Wrel[1], brel[1], Wroot[1],
               (const float*)nullptr, (const float*)nullptr, (const float*)nullptr, 0, 1);
    launch_pdl(k_aggr64, dim3(gW), B, 0, 1);
    launch_pdl(k_gemm64_mma<false>, dim3(g128), B, (size_t)SMEM_MMA,
               Wrel[2], brel[2], Wroot[2],
               (const float*)nullptr, (const float*)nullptr, (const float*)nullptr, 1, 0);
    launch_pdl(k_aggr64, dim3(gW), B, 0, 0);
    launch_pdl(k_gemm64_mma<true>, dim3(g128), B, (size_t)SMEM_MMA,
               Wrel[3], brel[3], Wroot[3],
               Wrel[4], brel[4], Wroot[4], 0, 0);

    // layer 4 aggregation (scalar) + sigmoid
    launch_pdl(k_final, dim3(gW), B, 0, out);
}

// round 16
// speedup vs baseline: 1.1672x; 1.1672x over previous
#include <cuda_runtime.h>
#include <math.h>

#define N_NODES 50000
#define N_EDGES 800000
#define SCAN_B  1024
#define SCAN_NB ((N_NODES + SCAN_B - 1) / SCAN_B)   // 49

// griddepcontrol (PDL)
#define PDL_TRIGGER() asm volatile("griddepcontrol.launch_dependents;" ::: "memory")
#define PDL_WAIT()    asm volatile("griddepcontrol.wait;" ::: "memory")

// ---------------- scratch (static device memory; no allocs) ----------------
__device__ int      g_counts[N_NODES];     // invariant: zero at kernel_launch entry
__device__ int      g_rowptr[N_NODES + 1];
__device__ int      g_rsv[N_EDGES];        // per-edge ticket within its dst segment
__device__ int      g_tmp[N_NODES];
__device__ int      g_bsum[64];
__device__ int2     g_edge[N_EDGES];       // {src, weight-as-int}
__device__ float    g_x16[N_NODES * 16];   // x padded 13 -> 16
__device__ float    g_h[2][N_NODES * 64];  // fp32 h
// aggr stored pre-split: per node row, words [0,32) = bf16x2 hi, [32,64) = lo.
__device__ unsigned g_aggrbf[N_NODES * 64];
__device__ float    g_aggr13[N_NODES * 16]; // layer0 aggregate (16-stride)
__device__ float    g_t[N_NODES];
__device__ float    g_r[N_NODES];

// ---------------- helpers ----------------
__device__ __forceinline__ unsigned cvt_bf2(float lo, float hi) {
    unsigned r;
    asm("cvt.rn.bf16x2.f32 %0, %1, %2;" : "=r"(r) : "f"(hi), "f"(lo));
    return r;
}
__device__ __forceinline__ float bf_lo(unsigned u) { return __uint_as_float(u << 16); }
__device__ __forceinline__ float bf_hi(unsigned u) { return __uint_as_float(u & 0xffff0000u); }

__device__ __forceinline__ void mma_bf16(float* c,
                                         unsigned a0, unsigned a1, unsigned a2, unsigned a3,
                                         unsigned b0, unsigned b1) {
    asm volatile(
        "mma.sync.aligned.m16n8k16.row.col.f32.bf16.bf16.f32 "
        "{%0,%1,%2,%3}, {%4,%5,%6,%7}, {%8,%9}, {%0,%1,%2,%3};\n"
        : "+f"(c[0]), "+f"(c[1]), "+f"(c[2]), "+f"(c[3])
        : "r"(a0), "r"(a1), "r"(a2), "r"(a3), "r"(b0), "r"(b1));
}

// ---------------- CSR build (R14 exact) -------------------------------------
__global__ void k_hist(const int* __restrict__ dst, const float* __restrict__ x) {
    PDL_TRIGGER();
    int gt = blockIdx.x * blockDim.x + threadIdx.x;
    int gs = gridDim.x * blockDim.x;
    for (int i = gt; i < N_NODES * 4; i += gs) {      // input-only: pre-wait
        int node = i >> 2, c = (i & 3) * 4;
        float4 v;
        v.x = (c + 0 < 13) ? __ldg(&x[node * 13 + c + 0]) : 0.f;
        v.y = (c + 1 < 13) ? __ldg(&x[node * 13 + c + 1]) : 0.f;
        v.z = (c + 2 < 13) ? __ldg(&x[node * 13 + c + 2]) : 0.f;
        v.w = (c + 3 < 13) ? __ldg(&x[node * 13 + c + 3]) : 0.f;
        ((float4*)g_x16)[i] = v;
    }
    int e2 = gt;
    int2 d = make_int2(0, 0);
    bool ok = (2 * e2 < N_EDGES);
    if (ok) d = __ldg((const int2*)dst + e2);
    PDL_WAIT();
    if (ok) {
        int t0 = atomicAdd(&g_counts[d.x], 1);
        int t1 = atomicAdd(&g_counts[d.y], 1);
        *(int2*)(g_rsv + 2 * e2) = make_int2(t0, t1);
    }
}

__global__ void k_scan_part() {
    PDL_TRIGGER();
    __shared__ int swarp[32];
    int tid = threadIdx.x, lane = tid & 31, wid = tid >> 5;
    int i = blockIdx.x * SCAN_B + tid;
    PDL_WAIT();
    int v = (i < N_NODES) ? g_counts[i] : 0;
#pragma unroll
    for (int o = 1; o < 32; o <<= 1) {
        int t = __shfl_up_sync(0xffffffffu, v, o);
        if (lane >= o) v += t;
    }
    if (lane == 31) swarp[wid] = v;
    __syncthreads();
    if (wid == 0) {
        int w = swarp[lane];
#pragma unroll
        for (int o = 1; o < 32; o <<= 1) {
            int t = __shfl_up_sync(0xffffffffu, w, o);
            if (lane >= o) w += t;
        }
        swarp[lane] = w;
    }
    __syncthreads();
    if (wid > 0) v += swarp[wid - 1];
    if (i < N_NODES) g_tmp[i] = v;
    if (tid == SCAN_B - 1) g_bsum[blockIdx.x] = v;
}

__global__ void k_scan_fin() {
    PDL_TRIGGER();
    __shared__ int soff;
    int tid = threadIdx.x;
    PDL_WAIT();
    if (tid < 32) {
        int v = 0;
        for (int j = tid; j < (int)blockIdx.x; j += 32) v += g_bsum[j];
#pragma unroll
        for (int o = 16; o > 0; o >>= 1) v += __shfl_xor_sync(0xffffffffu, v, o);
        if (tid == 0) soff = v;
    }
    __syncthreads();
    int off = soff;
    int i = blockIdx.x * SCAN_B + tid;
    if (i < N_NODES) {
        int incl = g_tmp[i] + off;
        int c = g_counts[i];
        g_rowptr[i] = incl - c;
        g_counts[i] = 0;                 // restore invariant for next replay
        if (i == N_NODES - 1) g_rowptr[N_NODES] = incl;
    }
}

__global__ void k_scatter(const int* __restrict__ src, const int* __restrict__ dst,
                          const float* __restrict__ ew) {
    PDL_TRIGGER();
    int e2 = blockIdx.x * blockDim.x + threadIdx.x;
    bool ok = (2 * e2 < N_EDGES);
    int2 s = make_int2(0, 0), d = make_int2(0, 0);
    float2 w = make_float2(0.f, 0.f);
    if (ok) {                              // harness inputs: pre-wait safe
        s = __ldg((const int2*)src + e2);
        d = __ldg((const int2*)dst + e2);
        w = __ldg((const float2*)ew + e2);
    }
    PDL_WAIT();
    if (ok) {
        int2 r = *(const int2*)(g_rsv + 2 * e2);
        g_edge[g_rowptr[d.x] + r.x] = make_int2(s.x, __float_as_int(w.x));
        g_edge[g_rowptr[d.y] + r.y] = make_int2(s.y, __float_as_int(w.y));
    }
}

// ---------------- layer-0 aggregation: warp per node (50k warps) ------------
// 8 edge-slots x 4 lanes x float4 over padded x16; single shfl-reduce tree.
__global__ void k_aggr13() {
    PDL_TRIGGER();
    PDL_WAIT();
    int w = (blockIdx.x * blockDim.x + threadIdx.x) >> 5;
    if (w >= N_NODES) return;
    int lane = threadIdx.x & 31, grp = lane >> 2, sl = lane & 3;
    const float4* __restrict__ x4 = (const float4*)g_x16;
    int i = g_rowptr[w] + grp, e = g_rowptr[w + 1];
    float4 a = make_float4(0.f, 0.f, 0.f, 0.f);
    for (; i < e; i += 8) {
        int2 r = __ldg(&g_edge[i]);
        float4 v = __ldg(x4 + r.x * 4 + sl);
        float ww = __int_as_float(r.y);
        a.x += ww * v.x; a.y += ww * v.y; a.z += ww * v.z; a.w += ww * v.w;
    }
#pragma unroll
    for (int o = 4; o < 32; o <<= 1) {
        a.x += __shfl_xor_sync(0xffffffffu, a.x, o);
        a.y += __shfl_xor_sync(0xffffffffu, a.y, o);
        a.z += __shfl_xor_sync(0xffffffffu, a.z, o);
        a.w += __shfl_xor_sync(0xffffffffu, a.w, o);
    }
    if (grp == 0) ((float4*)(g_aggr13 + (size_t)w * 16))[sl] = a;
}

// ---------------- GEMM 13->64 (FFMA, 64 nodes/block; proven R8 body) -------
__global__ __launch_bounds__(256) void k_gemm13(
    const float* __restrict__ x,
    const float* __restrict__ Wrel, const float* __restrict__ brel,
    const float* __restrict__ Wroot) {
    PDL_TRIGGER();
    __shared__ __align__(16) float sW[2 * 13 * 64];
    __shared__ float sb[64];
    int tid = threadIdx.x;
    for (int idx = tid; idx < 13 * 64; idx += 256) {   // harness inputs
        sW[idx]           = Wrel[idx];
        sW[13 * 64 + idx] = Wroot[idx];
    }
    if (tid < 64) sb[tid] = brel[tid];
    PDL_WAIT();
    __syncthreads();

    int node = blockIdx.x * 64 + (tid >> 2);
    int cq   = (tid & 3) * 4;
    int c0   = cq * 4;
    if (node >= N_NODES) return;
    float acc[16];
#pragma unroll
    for (int j = 0; j < 16; j++) acc[j] = sb[c0 + j];
    const float4* sWrel4  = (const float4*)sW;
    const float4* sWroot4 = (const float4*)(sW + 13 * 64);
#pragma unroll
    for (int k = 0; k < 13; k++) {
        float a  = __ldg(&g_aggr13[node * 16 + k]);
        float hk = __ldg(&x[node * 13 + k]);
#pragma unroll
        for (int j = 0; j < 4; j++) {
            float4 wr = sWrel4[k * 16 + cq + j];
            float4 ws = sWroot4[k * 16 + cq + j];
            acc[4 * j + 0] += a * wr.x + hk * ws.x;
            acc[4 * j + 1] += a * wr.y + hk * ws.y;
            acc[4 * j + 2] += a * wr.z + hk * ws.z;
            acc[4 * j + 3] += a * wr.w + hk * ws.w;
        }
    }
    float4* o4 = (float4*)(g_h[0] + (size_t)node * 64 + c0);
#pragma unroll
    for (int j = 0; j < 4; j++) {
        float4 v;
        v.x = fmaxf(acc[4 * j + 0], 0.f); v.y = fmaxf(acc[4 * j + 1], 0.f);
        v.z = fmaxf(acc[4 * j + 2], 0.f); v.w = fmaxf(acc[4 * j + 3], 0.f);
        o4[j] = v;
    }
}

// ---------------- aggregation: full warp per node (R14 exact) --------------
__global__ void k_aggr64(int sel) {
    PDL_TRIGGER();
    PDL_WAIT();
    int w = (blockIdx.x * blockDim.x + threadIdx.x) >> 5;
    if (w >= N_NODES) return;
    int lane = threadIdx.x & 31, half = lane >> 4, sl = lane & 15;
    const float4* __restrict__ h4 = (const float4*)g_h[sel];
    int i = g_rowptr[w] + half, e = g_rowptr[w + 1];
    float4 a = make_float4(0.f, 0.f, 0.f, 0.f);
    float4 b = make_float4(0.f, 0.f, 0.f, 0.f);
    for (; i + 2 < e; i += 4) {
        int2 r0 = __ldg(&g_edge[i]);
        int2 r1 = __ldg(&g_edge[i + 2]);
        float4 v0 = __ldg(h4 + r0.x * 16 + sl);
        float4 v1 = __ldg(h4 + r1.x * 16 + sl);
        float w0 = __int_as_float(r0.y), w1 = __int_as_float(r1.y);
        a.x += w0 * v0.x; a.y += w0 * v0.y; a.z += w0 * v0.z; a.w += w0 * v0.w;
        b.x += w1 * v1.x; b.y += w1 * v1.y; b.z += w1 * v1.z; b.w += w1 * v1.w;
    }
    if (i < e) {
        int2 r = __ldg(&g_edge[i]);
        float4 v = __ldg(h4 + r.x * 16 + sl);
        float ww = __int_as_float(r.y);
        a.x += ww * v.x; a.y += ww * v.y; a.z += ww * v.z; a.w += ww * v.w;
    }
    a.x += b.x; a.y += b.y; a.z += b.z; a.w += b.w;
    a.x += __shfl_xor_sync(0xffffffffu, a.x, 16);
    a.y += __shfl_xor_sync(0xffffffffu, a.y, 16);
    a.z += __shfl_xor_sync(0xffffffffu, a.z, 16);
    a.w += __shfl_xor_sync(0xffffffffu, a.w, 16);
    if (half == 0) {
        unsigned h0 = cvt_bf2(a.x, a.y);
        unsigned h1 = cvt_bf2(a.z, a.w);
        unsigned l0 = cvt_bf2(a.x - bf_lo(h0), a.y - bf_hi(h0));
        unsigned l1 = cvt_bf2(a.z - bf_lo(h1), a.w - bf_hi(h1));
        unsigned* ob = g_aggrbf + (size_t)w * 64;
        *(uint2*)(ob + 2 * sl)      = make_uint2(h0, h1);
        *(uint2*)(ob + 32 + 2 * sl) = make_uint2(l0, l1);
    }
}

// ---------------- GEMM 64->64 via bf16 3-term MMA (R14 exact) --------------
#define AW 68   // padded word stride (bank-conflict-free fragment loads)
template <bool FINAL>
__global__ __launch_bounds__(256) void k_gemm64_mma(
    const float* __restrict__ Wrel, const float* __restrict__ brel,
    const float* __restrict__ Wroot,
    const float* __restrict__ Wrel4, const float* __restrict__ b4,
    const float* __restrict__ Wroot4,
    int insel, int outsel) {
    PDL_TRIGGER();
    extern __shared__ unsigned smem_u[];
    unsigned* sAhi = smem_u;                    // 128*AW
    unsigned* sAlo = sAhi + 128 * AW;           // 128*AW
    unsigned* sWhi = sAlo + 128 * AW;           // 64*AW
    unsigned* sWlo = sWhi + 64 * AW;            // 64*AW
    float*    sb   = (float*)(sWlo + 64 * AW);  // 64

    int tid = threadIdx.x;
    const float* __restrict__ hin = g_h[insel];
    int nbase = blockIdx.x * 128;

    if (tid < 64) sb[tid] = brel[tid];

    for (int p = tid; p < 64 * 64; p += 256) {    // harness inputs: pre-wait
        int col = p >> 6, w = p & 63;
        int k = 2 * w;
        float f0, f1;
        if (k < 64) { f0 = __ldg(&Wrel[k * 64 + col]);         f1 = __ldg(&Wrel[(k + 1) * 64 + col]); }
        else        { f0 = __ldg(&Wroot[(k - 64) * 64 + col]); f1 = __ldg(&Wroot[(k - 63) * 64 + col]); }
        unsigned hi = cvt_bf2(f0, f1);
        sWhi[col * AW + w] = hi;
        sWlo[col * AW + w] = cvt_bf2(f0 - bf_lo(hi), f1 - bf_hi(hi));
    }
    PDL_WAIT();
    for (int p = tid; p < 128 * 16; p += 256) {
        int ln = p >> 4, w4 = p & 15;             // words 2*w4, 2*w4+1
        int node = nbase + ln;
        if (node >= N_NODES) node = N_NODES - 1;
        // aggr half: pre-split hi/lo, straight copy
        const unsigned* ar = g_aggrbf + (size_t)node * 64;
        uint2 ah = __ldg((const uint2*)ar + w4);
        uint2 al = __ldg((const uint2*)(ar + 32) + w4);
        sAhi[ln * AW + 2 * w4]     = ah.x;
        sAhi[ln * AW + 2 * w4 + 1] = ah.y;
        sAlo[ln * AW + 2 * w4]     = al.x;
        sAlo[ln * AW + 2 * w4 + 1] = al.y;
        // h half: fp32, split here
        float4 vh = __ldg((const float4*)(hin + (size_t)node * 64) + w4);
        unsigned h0 = cvt_bf2(vh.x, vh.y), h1 = cvt_bf2(vh.z, vh.w);
        sAhi[ln * AW + 32 + 2 * w4]     = h0;
        sAhi[ln * AW + 32 + 2 * w4 + 1] = h1;
        sAlo[ln * AW + 32 + 2 * w4]     = cvt_bf2(vh.x - bf_lo(h0), vh.y - bf_hi(h0));
        sAlo[ln * AW + 32 + 2 * w4 + 1] = cvt_bf2(vh.z - bf_lo(h1), vh.w - bf_hi(h1));
    }
    __syncthreads();

    int warp = tid >> 5, lane = tid & 31;
    int r = lane >> 2, q = lane & 3;
    int mb = warp * 16;

    float acc[8][4];
#pragma unroll
    for (int j = 0; j < 8; j++) {
        float b0 = sb[j * 8 + 2 * q], b1 = sb[j * 8 + 2 * q + 1];
        acc[j][0] = b0; acc[j][1] = b1; acc[j][2] = b0; acc[j][3] = b1;
    }

    int arow0 = (mb + r) * AW, arow1 = (mb + r + 8) * AW;
#pragma unroll
    for (int ks = 0; ks < 8; ks++) {
        int kw = ks * 8 + q;
        unsigned ah0 = sAhi[arow0 + kw],     ah1 = sAhi[arow1 + kw];
        unsigned ah2 = sAhi[arow0 + kw + 4], ah3 = sAhi[arow1 + kw + 4];
        unsigned al0 = sAlo[arow0 + kw],     al1 = sAlo[arow1 + kw];
        unsigned al2 = sAlo[arow0 + kw + 4], al3 = sAlo[arow1 + kw + 4];
#pragma unroll
        for (int j = 0; j < 8; j++) {
            int brow = (j * 8 + r) * AW + ks * 8 + q;
            unsigned bh0 = sWhi[brow], bh1 = sWhi[brow + 4];
            unsigned bl0 = sWlo[brow], bl1 = sWlo[brow + 4];
            mma_bf16(acc[j], ah0, ah1, ah2, ah3, bh0, bh1);
            mma_bf16(acc[j], ah0, ah1, ah2, ah3, bl0, bl1);
            mma_bf16(acc[j], al0, al1, al2, al3, bh0, bh1);
        }
    }

    int n0 = nbase + mb + r;      // row of c0/c1
    int n1 = n0 + 8;              // row of c2/c3
    if (FINAL) {
        float pt0 = 0.f, pr0 = 0.f, pt1 = 0.f, pr1 = 0.f;
#pragma unroll
        for (int j = 0; j < 8; j++) {
            int c = j * 8 + 2 * q;
            float w0 = __ldg(&Wrel4[c]),  w1 = __ldg(&Wrel4[c + 1]);
            float s0 = __ldg(&Wroot4[c]), s1 = __ldg(&Wroot4[c + 1]);
            float u;
            u = fmaxf(acc[j][0], 0.f); pt0 += u * w0; pr0 += u * s0;
            u = fmaxf(acc[j][1], 0.f); pt0 += u * w1; pr0 += u * s1;
            u = fmaxf(acc[j][2], 0.f); pt1 += u * w0; pr1 += u * s0;
            u = fmaxf(acc[j][3], 0.f); pt1 += u * w1; pr1 += u * s1;
        }
        pt0 += __shfl_xor_sync(0xffffffffu, pt0, 1);
        pt0 += __shfl_xor_sync(0xffffffffu, pt0, 2);
        pr0 += __shfl_xor_sync(0xffffffffu, pr0, 1);
        pr0 += __shfl_xor_sync(0xffffffffu, pr0, 2);
        pt1 += __shfl_xor_sync(0xffffffffu, pt1, 1);
        pt1 += __shfl_xor_sync(0xffffffffu, pt1, 2);
        pr1 += __shfl_xor_sync(0xffffffffu, pr1, 1);
        pr1 += __shfl_xor_sync(0xffffffffu, pr1, 2);
        float bb = __ldg(&b4[0]);
        if (q == 0) {
            if (n0 < N_NODES) { g_t[n0] = pt0; g_r[n0] = pr0 + bb; }
            if (n1 < N_NODES) { g_t[n1] = pt1; g_r[n1] = pr1 + bb; }
        }
    } else {
        float* ob = g_h[outsel];
#pragma unroll
        for (int j = 0; j < 8; j++) {
            int c = j * 8 + 2 * q;
            if (n0 < N_NODES)
                *(float2*)(ob + (size_t)n0 * 64 + c) =
                    make_float2(fmaxf(acc[j][0], 0.f), fmaxf(acc[j][1], 0.f));
            if (n1 < N_NODES)
                *(float2*)(ob + (size_t)n1 * 64 + c) =
                    make_float2(fmaxf(acc[j][2], 0.f), fmaxf(acc[j][3], 0.f));
        }
    }
}

// ---------------- final: out = sigmoid(segsum(w * t[src]) + r) -------------
__global__ void k_final(float* __restrict__ out) {
    PDL_TRIGGER();
    PDL_WAIT();
    int gw   = (blockIdx.x * blockDim.x + threadIdx.x) >> 5;
    int lane = threadIdx.x & 31;
    if (gw >= N_NODES) return;
    int start = g_rowptr[gw], end = g_rowptr[gw + 1];
    float acc = 0.f;
    for (int e = start + lane; e < end; e += 32) {
        int2 er = __ldg(&g_edge[e]);
        acc += __int_as_float(er.y) * __ldg(&g_t[er.x]);
    }
#pragma unroll
    for (int o = 16; o > 0; o >>= 1)
        acc += __shfl_xor_sync(0xffffffffu, acc, o);
    if (lane == 0) {
        float z = acc + g_r[gw];
        out[gw] = 1.f / (1.f + expf(-z));
    }
}

// ---------------- launch helpers ----------------
template <typename F, typename... Args>
static void launch_pdl(F f, dim3 g, dim3 b, size_t sm, Args... args) {
    cudaLaunchConfig_t cfg = {};
    cfg.gridDim = g;
    cfg.blockDim = b;
    cfg.dynamicSmemBytes = sm;
    cfg.stream = 0;
    cudaLaunchAttribute at[1];
    at[0].id = cudaLaunchAttributeProgrammaticStreamSerialization;
    at[0].val.programmaticStreamSerializationAllowed = 1;
    cfg.attrs = at;
    cfg.numAttrs = 1;
    cudaLaunchKernelEx(&cfg, f, args...);
}

extern "C" void kernel_launch(void* const* d_in, const int* in_sizes, int n_in,
                              void* d_out, int out_size) {
    const float* x  = (const float*)d_in[0];
    const int*   ei = (const int*)d_in[1];
    const float* ew = (const float*)d_in[2];
    const int* src = ei;
    const int* dst = ei + N_EDGES;

    const float* Wrel[5], * brel[5], * Wroot[5];
    for (int l = 0; l < 5; l++) {
        Wrel[l]  = (const float*)d_in[3 + 3 * l];
        brel[l]  = (const float*)d_in[4 + 3 * l];
        Wroot[l] = (const float*)d_in[5 + 3 * l];
    }
    float* out = (float*)d_out;

    const int SMEM_MMA = (128 * AW * 2 + 64 * AW * 2 + 64) * 4;   // 104704 B
    cudaFuncSetAttribute(k_gemm64_mma<false>,
                         cudaFuncAttributeMaxDynamicSharedMemorySize, SMEM_MMA);
    cudaFuncSetAttribute(k_gemm64_mma<true>,
                         cudaFuncAttributeMaxDynamicSharedMemorySize, SMEM_MMA);

    const int TB = 256;
    dim3 B(TB);
    int gE2  = (N_EDGES / 2 + TB - 1) / TB;       // 2 edges/thread (covers padx)
    int gW   = (N_NODES * 32 + TB - 1) / TB;      // warp-per-node
    int g64  = (N_NODES + 63) / 64;
    int g128 = (N_NODES + 127) / 128;

    // CSR build (g_counts zero by invariant)
    launch_pdl(k_hist, dim3(gE2), B, 0, dst, x);
    launch_pdl(k_scan_part, dim3(SCAN_NB), dim3(SCAN_B), 0);
    launch_pdl(k_scan_fin,  dim3(SCAN_NB), dim3(SCAN_B), 0);
    launch_pdl(k_scatter, dim3(gE2), B, 0, src, dst, ew);

    // layer 0: 13 -> 64 (standalone warp-per-node aggregation + GEMM)
    launch_pdl(k_aggr13, dim3(gW), B, 0);
    launch_pdl(k_gemm13, dim3(g64), B, 0, x, Wrel[0], brel[0], Wroot[0]);

    // layers 1-3: 64 -> 64 (layer 3 folds the 64->1 projection of layer 4)
    launch_pdl(k_aggr64, dim3(gW), B, 0, 0);
    launch_pdl(k_gemm64_mma<false>, dim3(g128), B, (size_t)SMEM_MMA,
               Wrel[1], brel[1], Wroot[1],
               (const float*)nullptr, (const float*)nullptr, (const float*)nullptr, 0, 1);
    launch_pdl(k_aggr64, dim3(gW), B, 0, 1);
    launch_pdl(k_gemm64_mma<false>, dim3(g128), B, (size_t)SMEM_MMA,
               Wrel[2], brel[2], Wroot[2],
               (const float*)nullptr, (const float*)nullptr, (const float*)nullptr, 1, 0);
    launch_pdl(k_aggr64, dim3(gW), B, 0, 0);
    launch_pdl(k_gemm64_mma<true>, dim3(g128), B, (size_t)SMEM_MMA,
               Wrel[3], brel[3], Wroot[3],
               Wrel[4], brel[4], Wroot[4], 0, 0);

    // layer 4 aggregation (scalar) + sigmoid
    launch_pdl(k_final, dim3(gW), B, 0, out);
}

// round 17
// speedup vs baseline: 1.2079x; 1.0348x over previous
#include <cuda_runtime.h>
#include <math.h>

#define N_NODES 50000
#define N_EDGES 800000
#define SCAN_B  1024
#define SCAN_NB ((N_NODES + SCAN_B - 1) / SCAN_B)   // 49

// griddepcontrol (PDL)
#define PDL_TRIGGER() asm volatile("griddepcontrol.launch_dependents;" ::: "memory")
#define PDL_WAIT()    asm volatile("griddepcontrol.wait;" ::: "memory")

// ---------------- scratch (static device memory; no allocs) ----------------
__device__ int      g_counts[N_NODES];     // invariant: zero at kernel_launch entry
__device__ int      g_rowptr[N_NODES + 1];
__device__ int      g_rsv[N_EDGES];        // per-edge ticket within its dst segment
__device__ int      g_tmp[N_NODES];
__device__ int      g_bsum[64];
__device__ __align__(16) int2 g_edge[N_EDGES];   // {src, weight-as-int}, 16B-alignable
__device__ float    g_x16[N_NODES * 16];   // x padded 13 -> 16
__device__ float    g_h[2][N_NODES * 64];  // fp32 h
// aggr stored pre-split: per node row, words [0,32) = bf16x2 hi, [32,64) = lo.
__device__ unsigned g_aggrbf[N_NODES * 64];
__device__ float    g_aggr13[N_NODES * 16]; // layer0 aggregate (16-stride)
__device__ float    g_t[N_NODES];
__device__ float    g_r[N_NODES];

// ---------------- helpers ----------------
__device__ __forceinline__ unsigned cvt_bf2(float lo, float hi) {
    unsigned r;
    asm("cvt.rn.bf16x2.f32 %0, %1, %2;" : "=r"(r) : "f"(hi), "f"(lo));
    return r;
}
__device__ __forceinline__ float bf_lo(unsigned u) { return __uint_as_float(u << 16); }
__device__ __forceinline__ float bf_hi(unsigned u) { return __uint_as_float(u & 0xffff0000u); }

__device__ __forceinline__ void mma_bf16(float* c,
                                         unsigned a0, unsigned a1, unsigned a2, unsigned a3,
                                         unsigned b0, unsigned b1) {
    asm volatile(
        "mma.sync.aligned.m16n8k16.row.col.f32.bf16.bf16.f32 "
        "{%0,%1,%2,%3}, {%4,%5,%6,%7}, {%8,%9}, {%0,%1,%2,%3};\n"
        : "+f"(c[0]), "+f"(c[1]), "+f"(c[2]), "+f"(c[3])
        : "r"(a0), "r"(a1), "r"(a2), "r"(a3), "r"(b0), "r"(b1));
}

// ---------------- CSR build (R16 exact) -------------------------------------
__global__ void k_hist(const int* __restrict__ dst, const float* __restrict__ x) {
    PDL_TRIGGER();
    int gt = blockIdx.x * blockDim.x + threadIdx.x;
    int gs = gridDim.x * blockDim.x;
    for (int i = gt; i < N_NODES * 4; i += gs) {      // input-only: pre-wait
        int node = i >> 2, c = (i & 3) * 4;
        float4 v;
        v.x = (c + 0 < 13) ? __ldg(&x[node * 13 + c + 0]) : 0.f;
        v.y = (c + 1 < 13) ? __ldg(&x[node * 13 + c + 1]) : 0.f;
        v.z = (c + 2 < 13) ? __ldg(&x[node * 13 + c + 2]) : 0.f;
        v.w = (c + 3 < 13) ? __ldg(&x[node * 13 + c + 3]) : 0.f;
        ((float4*)g_x16)[i] = v;
    }
    int e2 = gt;
    int2 d = make_int2(0, 0);
    bool ok = (2 * e2 < N_EDGES);
    if (ok) d = __ldg((const int2*)dst + e2);
    PDL_WAIT();
    if (ok) {
        int t0 = atomicAdd(&g_counts[d.x], 1);
        int t1 = atomicAdd(&g_counts[d.y], 1);
        *(int2*)(g_rsv + 2 * e2) = make_int2(t0, t1);
    }
}

__global__ void k_scan_part() {
    PDL_TRIGGER();
    __shared__ int swarp[32];
    int tid = threadIdx.x, lane = tid & 31, wid = tid >> 5;
    int i = blockIdx.x * SCAN_B + tid;
    PDL_WAIT();
    int v = (i < N_NODES) ? g_counts[i] : 0;
#pragma unroll
    for (int o = 1; o < 32; o <<= 1) {
        int t = __shfl_up_sync(0xffffffffu, v, o);
        if (lane >= o) v += t;
    }
    if (lane == 31) swarp[wid] = v;
    __syncthreads();
    if (wid == 0) {
        int w = swarp[lane];
#pragma unroll
        for (int o = 1; o < 32; o <<= 1) {
            int t = __shfl_up_sync(0xffffffffu, w, o);
            if (lane >= o) w += t;
        }
        swarp[lane] = w;
    }
    __syncthreads();
    if (wid > 0) v += swarp[wid - 1];
    if (i < N_NODES) g_tmp[i] = v;
    if (tid == SCAN_B - 1) g_bsum[blockIdx.x] = v;
}

__global__ void k_scan_fin() {
    PDL_TRIGGER();
    __shared__ int soff;
    int tid = threadIdx.x;
    PDL_WAIT();
    if (tid < 32) {
        int v = 0;
        for (int j = tid; j < (int)blockIdx.x; j += 32) v += g_bsum[j];
#pragma unroll
        for (int o = 16; o > 0; o >>= 1) v += __shfl_xor_sync(0xffffffffu, v, o);
        if (tid == 0) soff = v;
    }
    __syncthreads();
    int off = soff;
    int i = blockIdx.x * SCAN_B + tid;
    if (i < N_NODES) {
        int incl = g_tmp[i] + off;
        int c = g_counts[i];
        g_rowptr[i] = incl - c;
        g_counts[i] = 0;                 // restore invariant for next replay
        if (i == N_NODES - 1) g_rowptr[N_NODES] = incl;
    }
}

__global__ void k_scatter(const int* __restrict__ src, const int* __restrict__ dst,
                          const float* __restrict__ ew) {
    PDL_TRIGGER();
    int e2 = blockIdx.x * blockDim.x + threadIdx.x;
    bool ok = (2 * e2 < N_EDGES);
    int2 s = make_int2(0, 0), d = make_int2(0, 0);
    float2 w = make_float2(0.f, 0.f);
    if (ok) {                              // harness inputs: pre-wait safe
        s = __ldg((const int2*)src + e2);
        d = __ldg((const int2*)dst + e2);
        w = __ldg((const float2*)ew + e2);
    }
    PDL_WAIT();
    if (ok) {
        int2 r = *(const int2*)(g_rsv + 2 * e2);
        g_edge[g_rowptr[d.x] + r.x] = make_int2(s.x, __float_as_int(w.x));
        g_edge[g_rowptr[d.y] + r.y] = make_int2(s.y, __float_as_int(w.y));
    }
}

// ---------------- layer-0 aggregation: warp per node (R16 exact) -----------
__global__ void k_aggr13() {
    PDL_TRIGGER();
    PDL_WAIT();
    int w = (blockIdx.x * blockDim.x + threadIdx.x) >> 5;
    if (w >= N_NODES) return;
    int lane = threadIdx.x & 31, grp = lane >> 2, sl = lane & 3;
    const float4* __restrict__ x4 = (const float4*)g_x16;
    int i = g_rowptr[w] + grp, e = g_rowptr[w + 1];
    float4 a = make_float4(0.f, 0.f, 0.f, 0.f);
    for (; i < e; i += 8) {
        int2 r = __ldg(&g_edge[i]);
        float4 v = __ldg(x4 + r.x * 4 + sl);
        float ww = __int_as_float(r.y);
        a.x += ww * v.x; a.y += ww * v.y; a.z += ww * v.z; a.w += ww * v.w;
    }
#pragma unroll
    for (int o = 4; o < 32; o <<= 1) {
        a.x += __shfl_xor_sync(0xffffffffu, a.x, o);
        a.y += __shfl_xor_sync(0xffffffffu, a.y, o);
        a.z += __shfl_xor_sync(0xffffffffu, a.z, o);
        a.w += __shfl_xor_sync(0xffffffffu, a.w, o);
    }
    if (grp == 0) ((float4*)(g_aggr13 + (size_t)w * 16))[sl] = a;
}

// ---------------- GEMM 13->64 (R16 exact) ----------------------------------
__global__ __launch_bounds__(256) void k_gemm13(
    const float* __restrict__ x,
    const float* __restrict__ Wrel, const float* __restrict__ brel,
    const float* __restrict__ Wroot) {
    PDL_TRIGGER();
    __shared__ __align__(16) float sW[2 * 13 * 64];
    __shared__ float sb[64];
    int tid = threadIdx.x;
    for (int idx = tid; idx < 13 * 64; idx += 256) {   // harness inputs
        sW[idx]           = Wrel[idx];
        sW[13 * 64 + idx] = Wroot[idx];
    }
    if (tid < 64) sb[tid] = brel[tid];
    PDL_WAIT();
    __syncthreads();

    int node = blockIdx.x * 64 + (tid >> 2);
    int cq   = (tid & 3) * 4;
    int c0   = cq * 4;
    if (node >= N_NODES) return;
    float acc[16];
#pragma unroll
    for (int j = 0; j < 16; j++) acc[j] = sb[c0 + j];
    const float4* sWrel4  = (const float4*)sW;
    const float4* sWroot4 = (const float4*)(sW + 13 * 64);
#pragma unroll
    for (int k = 0; k < 13; k++) {
        float a  = __ldg(&g_aggr13[node * 16 + k]);
        float hk = __ldg(&x[node * 13 + k]);
#pragma unroll
        for (int j = 0; j < 4; j++) {
            float4 wr = sWrel4[k * 16 + cq + j];
            float4 ws = sWroot4[k * 16 + cq + j];
            acc[4 * j + 0] += a * wr.x + hk * ws.x;
            acc[4 * j + 1] += a * wr.y + hk * ws.y;
            acc[4 * j + 2] += a * wr.z + hk * ws.z;
            acc[4 * j + 3] += a * wr.w + hk * ws.w;
        }
    }
    float4* o4 = (float4*)(g_h[0] + (size_t)node * 64 + c0);
#pragma unroll
    for (int j = 0; j < 4; j++) {
        float4 v;
        v.x = fmaxf(acc[4 * j + 0], 0.f); v.y = fmaxf(acc[4 * j + 1], 0.f);
        v.z = fmaxf(acc[4 * j + 2], 0.f); v.w = fmaxf(acc[4 * j + 3], 0.f);
        o4[j] = v;
    }
}

// ---------------- aggregation v4: contiguous halves + paired edge loads ----
// half0 takes edges [s, m), half1 [m, e), m = s + ceil(len/2): trip counts
// differ by <=1. Each half loads 2 contiguous edges per LDG.128 (int4).
__global__ void k_aggr64(int sel) {
    PDL_TRIGGER();
    PDL_WAIT();
    int w = (blockIdx.x * blockDim.x + threadIdx.x) >> 5;
    if (w >= N_NODES) return;
    int lane = threadIdx.x & 31, half = lane >> 4, sl = lane & 15;
    const float4* __restrict__ h4 = (const float4*)g_h[sel];
    int s = g_rowptr[w], e = g_rowptr[w + 1];
    int m = s + ((e - s + 1) >> 1);
    int i  = half ? m : s;
    int ie = half ? e : m;
    float4 a = make_float4(0.f, 0.f, 0.f, 0.f);
    float4 b = make_float4(0.f, 0.f, 0.f, 0.f);
    // prologue: align i to even for int4 (16B) paired loads
    if ((i & 1) && i < ie) {
        int2 r = __ldg(&g_edge[i]);
        float4 v = __ldg(h4 + r.x * 16 + sl);
        float ww = __int_as_float(r.y);
        a.x += ww * v.x; a.y += ww * v.y; a.z += ww * v.z; a.w += ww * v.w;
        i++;
    }
    // main: 2 paired loads = 4 edges, 4 independent row loads in flight
    for (; i + 4 <= ie; i += 4) {
        int4 p0 = __ldg((const int4*)(g_edge + i));        // edges i, i+1
        int4 p1 = __ldg((const int4*)(g_edge + i + 2));    // edges i+2, i+3
        float4 v0 = __ldg(h4 + p0.x * 16 + sl);
        float4 v1 = __ldg(h4 + p0.z * 16 + sl);
        float4 v2 = __ldg(h4 + p1.x * 16 + sl);
        float4 v3 = __ldg(h4 + p1.z * 16 + sl);
        float w0 = __int_as_float(p0.y), w1 = __int_as_float(p0.w);
        float w2 = __int_as_float(p1.y), w3 = __int_as_float(p1.w);
        a.x += w0 * v0.x + w1 * v1.x;  a.y += w0 * v0.y + w1 * v1.y;
        a.z += w0 * v0.z + w1 * v1.z;  a.w += w0 * v0.w + w1 * v1.w;
        b.x += w2 * v2.x + w3 * v3.x;  b.y += w2 * v2.y + w3 * v3.y;
        b.z += w2 * v2.z + w3 * v3.z;  b.w += w2 * v2.w + w3 * v3.w;
    }
    if (i + 2 <= ie) {
        int4 p0 = __ldg((const int4*)(g_edge + i));
        float4 v0 = __ldg(h4 + p0.x * 16 + sl);
        float4 v1 = __ldg(h4 + p0.z * 16 + sl);
        float w0 = __int_as_float(p0.y), w1 = __int_as_float(p0.w);
        a.x += w0 * v0.x + w1 * v1.x;  a.y += w0 * v0.y + w1 * v1.y;
        a.z += w0 * v0.z + w1 * v1.z;  a.w += w0 * v0.w + w1 * v1.w;
        i += 2;
    }
    if (i < ie) {
        int2 r = __ldg(&g_edge[i]);
        float4 v = __ldg(h4 + r.x * 16 + sl);
        float ww = __int_as_float(r.y);
        a.x += ww * v.x; a.y += ww * v.y; a.z += ww * v.z; a.w += ww * v.w;
    }
    a.x += b.x; a.y += b.y; a.z += b.z; a.w += b.w;
    a.x += __shfl_xor_sync(0xffffffffu, a.x, 16);
    a.y += __shfl_xor_sync(0xffffffffu, a.y, 16);
    a.z += __shfl_xor_sync(0xffffffffu, a.z, 16);
    a.w += __shfl_xor_sync(0xffffffffu, a.w, 16);
    if (half == 0) {
        unsigned h0 = cvt_bf2(a.x, a.y);
        unsigned h1 = cvt_bf2(a.z, a.w);
        unsigned l0 = cvt_bf2(a.x - bf_lo(h0), a.y - bf_hi(h0));
        unsigned l1 = cvt_bf2(a.z - bf_lo(h1), a.w - bf_hi(h1));
        unsigned* ob = g_aggrbf + (size_t)w * 64;
        *(uint2*)(ob + 2 * sl)      = make_uint2(h0, h1);
        *(uint2*)(ob + 32 + 2 * sl) = make_uint2(l0, l1);
    }
}

// ---------------- GEMM 64->64 via bf16 3-term MMA (R16 exact) --------------
#define AW 68   // padded word stride (bank-conflict-free fragment loads)
template <bool FINAL>
__global__ __launch_bounds__(256) void k_gemm64_mma(
    const float* __restrict__ Wrel, const float* __restrict__ brel,
    const float* __restrict__ Wroot,
    const float* __restrict__ Wrel4, const float* __restrict__ b4,
    const float* __restrict__ Wroot4,
    int insel, int outsel) {
    PDL_TRIGGER();
    extern __shared__ unsigned smem_u[];
    unsigned* sAhi = smem_u;                    // 128*AW
    unsigned* sAlo = sAhi + 128 * AW;           // 128*AW
    unsigned* sWhi = sAlo + 128 * AW;           // 64*AW
    unsigned* sWlo = sWhi + 64 * AW;            // 64*AW
    float*    sb   = (float*)(sWlo + 64 * AW);  // 64

    int tid = threadIdx.x;
    const float* __restrict__ hin = g_h[insel];
    int nbase = blockIdx.x * 128;

    if (tid < 64) sb[tid] = brel[tid];

    for (int p = tid; p < 64 * 64; p += 256) {    // harness inputs: pre-wait
        int col = p >> 6, w = p & 63;
        int k = 2 * w;
        float f0, f1;
        if (k < 64) { f0 = __ldg(&Wrel[k * 64 + col]);         f1 = __ldg(&Wrel[(k + 1) * 64 + col]); }
        else        { f0 = __ldg(&Wroot[(k - 64) * 64 + col]); f1 = __ldg(&Wroot[(k - 63) * 64 + col]); }
        unsigned hi = cvt_bf2(f0, f1);
        sWhi[col * AW + w] = hi;
        sWlo[col * AW + w] = cvt_bf2(f0 - bf_lo(hi), f1 - bf_hi(hi));
    }
    PDL_WAIT();
    for (int p = tid; p < 128 * 16; p += 256) {
        int ln = p >> 4, w4 = p & 15;             // words 2*w4, 2*w4+1
        int node = nbase + ln;
        if (node >= N_NODES) node = N_NODES - 1;
        const unsigned* ar = g_aggrbf + (size_t)node * 64;
        uint2 ah = __ldg((const uint2*)ar + w4);
        uint2 al = __ldg((const uint2*)(ar + 32) + w4);
        sAhi[ln * AW + 2 * w4]     = ah.x;
        sAhi[ln * AW + 2 * w4 + 1] = ah.y;
        sAlo[ln * AW + 2 * w4]     = al.x;
        sAlo[ln * AW + 2 * w4 + 1] = al.y;
        float4 vh = __ldg((const float4*)(hin + (size_t)node * 64) + w4);
        unsigned h0 = cvt_bf2(vh.x, vh.y), h1 = cvt_bf2(vh.z, vh.w);
        sAhi[ln * AW + 32 + 2 * w4]     = h0;
        sAhi[ln * AW + 32 + 2 * w4 + 1] = h1;
        sAlo[ln * AW + 32 + 2 * w4]     = cvt_bf2(vh.x - bf_lo(h0), vh.y - bf_hi(h0));
        sAlo[ln * AW + 32 + 2 * w4 + 1] = cvt_bf2(vh.z - bf_lo(h1), vh.w - bf_hi(h1));
    }
    __syncthreads();

    int warp = tid >> 5, lane = tid & 31;
    int r = lane >> 2, q = lane & 3;
    int mb = warp * 16;

    float acc[8][4];
#pragma unroll
    for (int j = 0; j < 8; j++) {
        float b0 = sb[j * 8 + 2 * q], b1 = sb[j * 8 + 2 * q + 1];
        acc[j][0] = b0; acc[j][1] = b1; acc[j][2] = b0; acc[j][3] = b1;
    }

    int arow0 = (mb + r) * AW, arow1 = (mb + r + 8) * AW;
#pragma unroll
    for (int ks = 0; ks < 8; ks++) {
        int kw = ks * 8 + q;
        unsigned ah0 = sAhi[arow0 + kw],     ah1 = sAhi[arow1 + kw];
        unsigned ah2 = sAhi[arow0 + kw + 4], ah3 = sAhi[arow1 + kw + 4];
        unsigned al0 = sAlo[arow0 + kw],     al1 = sAlo[arow1 + kw];
        unsigned al2 = sAlo[arow0 + kw + 4], al3 = sAlo[arow1 + kw + 4];
#pragma unroll
        for (int j = 0; j < 8; j++) {
            int brow = (j * 8 + r) * AW + ks * 8 + q;
            unsigned bh0 = sWhi[brow], bh1 = sWhi[brow + 4];
            unsigned bl0 = sWlo[brow], bl1 = sWlo[brow + 4];
            mma_bf16(acc[j], ah0, ah1, ah2, ah3, bh0, bh1);
            mma_bf16(acc[j], ah0, ah1, ah2, ah3, bl0, bl1);
            mma_bf16(acc[j], al0, al1, al2, al3, bh0, bh1);
        }
    }

    int n0 = nbase + mb + r;      // row of c0/c1
    int n1 = n0 + 8;              // row of c2/c3
    if (FINAL) {
        float pt0 = 0.f, pr0 = 0.f, pt1 = 0.f, pr1 = 0.f;
#pragma unroll
        for (int j = 0; j < 8; j++) {
            int c = j * 8 + 2 * q;
            float w0 = __ldg(&Wrel4[c]),  w1 = __ldg(&Wrel4[c + 1]);
            float s0 = __ldg(&Wroot4[c]), s1 = __ldg(&Wroot4[c + 1]);
            float u;
            u = fmaxf(acc[j][0], 0.f); pt0 += u * w0; pr0 += u * s0;
            u = fmaxf(acc[j][1], 0.f); pt0 += u * w1; pr0 += u * s1;
            u = fmaxf(acc[j][2], 0.f); pt1 += u * w0; pr1 += u * s0;
            u = fmaxf(acc[j][3], 0.f); pt1 += u * w1; pr1 += u * s1;
        }
        pt0 += __shfl_xor_sync(0xffffffffu, pt0, 1);
        pt0 += __shfl_xor_sync(0xffffffffu, pt0, 2);
        pr0 += __shfl_xor_sync(0xffffffffu, pr0, 1);
        pr0 += __shfl_xor_sync(0xffffffffu, pr0, 2);
        pt1 += __shfl_xor_sync(0xffffffffu, pt1, 1);
        pt1 += __shfl_xor_sync(0xffffffffu, pt1, 2);
        pr1 += __shfl_xor_sync(0xffffffffu, pr1, 1);
        pr1 += __shfl_xor_sync(0xffffffffu, pr1, 2);
        float bb = __ldg(&b4[0]);
        if (q == 0) {
            if (n0 < N_NODES) { g_t[n0] = pt0; g_r[n0] = pr0 + bb; }
            if (n1 < N_NODES) { g_t[n1] = pt1; g_r[n1] = pr1 + bb; }
        }
    } else {
        float* ob = g_h[outsel];
#pragma unroll
        for (int j = 0; j < 8; j++) {
            int c = j * 8 + 2 * q;
            if (n0 < N_NODES)
                *(float2*)(ob + (size_t)n0 * 64 + c) =
                    make_float2(fmaxf(acc[j][0], 0.f), fmaxf(acc[j][1], 0.f));
            if (n1 < N_NODES)
                *(float2*)(ob + (size_t)n1 * 64 + c) =
                    make_float2(fmaxf(acc[j][2], 0.f), fmaxf(acc[j][3], 0.f));
        }
    }
}

// ---------------- final: out = sigmoid(segsum(w * t[src]) + r) -------------
__global__ void k_final(float* __restrict__ out) {
    PDL_TRIGGER();
    PDL_WAIT();
    int gw   = (blockIdx.x * blockDim.x + threadIdx.x) >> 5;
    int lane = threadIdx.x & 31;
    if (gw >= N_NODES) return;
    int start = g_rowptr[gw], end = g_rowptr[gw + 1];
    float acc = 0.f;
    for (int e = start + lane; e < end; e += 32) {
        int2 er = __ldg(&g_edge[e]);
        acc += __int_as_float(er.y) * __ldg(&g_t[er.x]);
    }
#pragma unroll
    for (int o = 16; o > 0; o >>= 1)
        acc += __shfl_xor_sync(0xffffffffu, acc, o);
    if (lane == 0) {
        float z = acc + g_r[gw];
        out[gw] = 1.f / (1.f + expf(-z));
    }
}

// ---------------- launch helpers ----------------
template <typename F, typename... Args>
static void launch_pdl(F f, dim3 g, dim3 b, size_t sm, Args... args) {
    cudaLaunchConfig_t cfg = {};
    cfg.gridDim = g;
    cfg.blockDim = b;
    cfg.dynamicSmemBytes = sm;
    cfg.stream = 0;
    cudaLaunchAttribute at[1];
    at[0].id = cudaLaunchAttributeProgrammaticStreamSerialization;
    at[0].val.programmaticStreamSerializationAllowed = 1;
    cfg.attrs = at;
    cfg.numAttrs = 1;
    cudaLaunchKernelEx(&cfg, f, args...);
}

extern "C" void kernel_launch(void* const* d_in, const int* in_sizes, int n_in,
                              void* d_out, int out_size) {
    const float* x  = (const float*)d_in[0];
    const int*   ei = (const int*)d_in[1];
    const float* ew = (const float*)d_in[2];
    const int* src = ei;
    const int* dst = ei + N_EDGES;

    const float* Wrel[5], * brel[5], * Wroot[5];
    for (int l = 0; l < 5; l++) {
        Wrel[l]  = (const float*)d_in[3 + 3 * l];
        brel[l]  = (const float*)d_in[4 + 3 * l];
        Wroot[l] = (const float*)d_in[5 + 3 * l];
    }
    float* out = (float*)d_out;

    const int SMEM_MMA = (128 * AW * 2 + 64 * AW * 2 + 64) * 4;   // 104704 B
    cudaFuncSetAttribute(k_gemm64_mma<false>,
                         cudaFuncAttributeMaxDynamicSharedMemorySize, SMEM_MMA);
    cudaFuncSetAttribute(k_gemm64_mma<true>,
                         cudaFuncAttributeMaxDynamicSharedMemorySize, SMEM_MMA);

    const int TB = 256;
    dim3 B(TB);
    int gE2  = (N_EDGES / 2 + TB - 1) / TB;       // 2 edges/thread (covers padx)
    int gW   = (N_NODES * 32 + TB - 1) / TB;      // warp-per-node
    int g64  = (N_NODES + 63) / 64;
    int g128 = (N_NODES + 127) / 128;

    // CSR build (g_counts zero by invariant)
    launch_pdl(k_hist, dim3(gE2), B, 0, dst, x);
    launch_pdl(k_scan_part, dim3(SCAN_NB), dim3(SCAN_B), 0);
    launch_pdl(k_scan_fin,  dim3(SCAN_NB), dim3(SCAN_B), 0);
    launch_pdl(k_scatter, dim3(gE2), B, 0, src, dst, ew);

    // layer 0: 13 -> 64 (standalone warp-per-node aggregation + GEMM)
    launch_pdl(k_aggr13, dim3(gW), B, 0);
    launch_pdl(k_gemm13, dim3(g64), B, 0, x, Wrel[0], brel[0], Wroot[0]);

    // layers 1-3: 64 -> 64 (layer 3 folds the 64->1 projection of layer 4)
    launch_pdl(k_aggr64, dim3(gW), B, 0, 0);
    launch_pdl(k_gemm64_mma<false>, dim3(g128), B, (size_t)SMEM_MMA,
               Wrel[1], brel[1], Wroot[1],
               (const float*)nullptr, (const float*)nullptr, (const float*)nullptr, 0, 1);
    launch_pdl(k_aggr64, dim3(gW), B, 0, 1);
    launch_pdl(k_gemm64_mma<false>, dim3(g128), B, (size_t)SMEM_MMA,
               Wrel[2], brel[2], Wroot[2],
               (const float*)nullptr, (const float*)nullptr, (const float*)nullptr, 1, 0);
    launch_pdl(k_aggr64, dim3(gW), B, 0, 0);
    launch_pdl(k_gemm64_mma<true>, dim3(g128), B, (size_t)SMEM_MMA,
               Wrel[3], brel[3], Wroot[3],
               Wrel[4], brel[4], Wroot[4], 0, 0);

    // layer 4 aggregation (scalar) + sigmoid
    launch_pdl(k_final, dim3(gW), B, 0, out);
}